// round 6
// baseline (speedup 1.0000x reference)
#include <cuda_runtime.h>
#include <cstdint>

typedef unsigned long long u64;

#define BATCH 32
#define HID   64
#define CHUNK 2048
#define LOGC  11

__device__ __forceinline__ u64 fma2(u64 a, u64 b, u64 c){
    u64 d; asm("fma.rn.f32x2 %0, %1, %2, %3;" : "=l"(d) : "l"(a), "l"(b), "l"(c)); return d;
}
__device__ __forceinline__ u64 add2(u64 a, u64 b){
    u64 d; asm("add.rn.f32x2 %0, %1, %2;" : "=l"(d) : "l"(a), "l"(b)); return d;
}
__device__ __forceinline__ float hsum2(u64 a){
    float lo, hi; asm("mov.b64 {%0,%1}, %2;" : "=f"(lo), "=f"(hi) : "l"(a)); return lo + hi;
}
__device__ __forceinline__ float ex2f(float a){
    float d; asm("ex2.approx.f32 %0, %1;" : "=f"(d) : "f"(a)); return d;
}
__device__ __forceinline__ float rcpf(float a){
    float d; asm("rcp.approx.f32 %0, %1;" : "=f"(d) : "f"(a)); return d;
}

#define L2E      1.4426950408889634f
#define NEG_L2E (-1.4426950408889634f)
#define TWO_L2E  2.8853900817779268f

// One CTA per batch row (32 CTAs, each alone on an SM). 128 threads; pair
// (2i,2i+1) owns hidden unit i. Lane p=0: full 64-dot for r; p=1: full 64-dot
// for z; both lanes: half 32-dot for n (combined via shfl_xor 1).
//
// Critical-path tricks:
//  - EVERY lane computes the tanh tail with r := its own sigma (correct on
//    lane0, bounded-garbage on lane1). Only z crosses lanes (shfl), and z is
//    consumed at the last FMA where it has slack. Removes the shfl from the
//    sigma->tanh path. Only p=0 stores h / states.
//  - ex2 args fused: all log2e scalings folded into precomputed constants.
//  - branch-free inner loop (chunked x prefetch), explicit hbuf ping-pong,
//    hprev in register.
__global__ void __launch_bounds__(128, 1)
gru_kernel(const float* __restrict__ x, const float* __restrict__ w_ih,
           const float* __restrict__ w_hh, const float* __restrict__ b_ih,
           const float* __restrict__ b_hh, float* __restrict__ states, int T)
{
    __shared__ __align__(16) float hbuf[2][HID];
    __shared__ __align__(16) float xs[2][CHUNK];

    const int tid = threadIdx.x;
    const int b   = blockIdx.x;
    const int i   = tid >> 1;
    const int p   = tid & 1;
    const int ia  = i + 64 * p;        // r-row (p=0) or z-row (p=1)
    const int in_ = 128 + i;           // n-row

    // weights into registers (packed f32x2)
    u64 wa[32];
    {
        const u64* was = (const u64*)(w_hh + ia * 64);
        #pragma unroll
        for (int q = 0; q < 32; q++) wa[q] = was[q];
    }
    u64 wn[16];
    {
        const u64* wns = (const u64*)(w_hh + in_ * 64 + 32 * p);
        #pragma unroll
        for (int q = 0; q < 16; q++) wn[q] = wns[q];
    }

    // fused activation constants
    const float wih_a = w_ih[ia];
    const float ca    = b_hh[ia] + b_ih[ia];
    const float wihaL = wih_a * NEG_L2E;          // for sigma ex2 arg
    const float caL   = ca * NEG_L2E;
    const float wihn2 = w_ih[in_] * TWO_L2E;      // for tanh ex2 arg
    const float bihn2 = b_ih[in_] * TWO_L2E;
    const float bhhn2 = b_hh[in_] * TWO_L2E;

    const float* xrow = x + (size_t)b * T;

    if (tid < HID) hbuf[0][tid] = 0.0f;
    {
        const float4* src = (const float4*)xrow;
        float4* dst = (float4*)xs[0];
        #pragma unroll
        for (int q = 0; q < CHUNK / 4 / 128; q++) dst[tid + q * 128] = src[tid + q * 128];
    }
    __syncthreads();

    float* sout = states + ((size_t)b * T) * HID + i;
    float hprev = 0.0f;
    const int nch = T >> LOGC;

    // one GRU step: read h from HC, write new h to HD
    auto step = [&](const float* hc, float* hd, float xt, float* sp) {
        const float xac = fmaf(xt, wihaL, caL);    // -log2e * (x-part of gate a)
        const float xn2 = fmaf(xt, wihn2, bihn2);  // 2*log2e * (x-part of n)

        // full 64-dot for gate a (r or z): 8 accumulators
        u64 a0=0,a1=0,a2=0,a3=0,a4=0,a5=0,a6=0,a7=0;
        const ulonglong2* hs = (const ulonglong2*)hc;
        #pragma unroll
        for (int q = 0; q < 4; q++) {
            ulonglong2 h0 = hs[4*q], h1 = hs[4*q+1], h2 = hs[4*q+2], h3 = hs[4*q+3];
            a0 = fma2(h0.x, wa[8*q],   a0);  a1 = fma2(h0.y, wa[8*q+1], a1);
            a2 = fma2(h1.x, wa[8*q+2], a2);  a3 = fma2(h1.y, wa[8*q+3], a3);
            a4 = fma2(h2.x, wa[8*q+4], a4);  a5 = fma2(h2.y, wa[8*q+5], a5);
            a6 = fma2(h3.x, wa[8*q+6], a6);  a7 = fma2(h3.y, wa[8*q+7], a7);
        }
        float sa = hsum2(add2(add2(add2(a0,a1),add2(a2,a3)),
                              add2(add2(a4,a5),add2(a6,a7))));
        // sigma of own gate: sigma(v) = 1/(1+2^(-v*log2e))
        float ga = rcpf(1.0f + ex2f(fmaf(sa, NEG_L2E, xac)));
        float gz = __shfl_xor_sync(0xffffffffu, ga, 1);   // z for p=0 (latency hidden under tanh)

        // half 32-dot for n-gate (16 u64 = 32 floats)
        u64 n0=0,n1=0,n2=0,n3=0;
        const ulonglong2* hsn = (const ulonglong2*)(hc + 32 * p);
        #pragma unroll
        for (int q = 0; q < 4; q++) {
            ulonglong2 h0 = hsn[2*q], h1 = hsn[2*q+1];
            n0 = fma2(h0.x, wn[4*q],   n0);  n1 = fma2(h0.y, wn[4*q+1], n1);
            n2 = fma2(h1.x, wn[4*q+2], n2);  n3 = fma2(h1.y, wn[4*q+3], n3);
        }
        float snp = hsum2(add2(add2(n0,n1),add2(n2,n3)));
        float sn  = snp + __shfl_xor_sync(0xffffffffu, snp, 1);

        // tanh tail computed by BOTH lanes with r := ga (only lane0's is real)
        float hn2 = fmaf(sn, TWO_L2E, bhhn2);              // 2*log2e*(hn)
        float e2  = ex2f(fmaf(ga, hn2, xn2));              // exp(2u)
        float nv  = fmaf(-2.0f, rcpf(e2 + 1.0f), 1.0f);    // tanh(u)
        float hnew = fmaf(gz, hprev - nv, nv);             // (1-z)*n + z*h
        hprev = hnew;

        if (!p) {
            hd[i] = hnew;
            __stcs(sp, hnew);
        }
        __syncthreads();
    };

    for (int c = 0; c < nch; c++) {
        if (c + 1 < nch) {  // prefetch next chunk: one branch per 2048 steps
            const float4* src = (const float4*)(xrow + (size_t)(c + 1) * CHUNK);
            float4* dst = (float4*)xs[(c + 1) & 1];
            #pragma unroll
            for (int q = 0; q < CHUNK / 4 / 128; q++) dst[tid + q * 128] = src[tid + q * 128];
        }
        const float* xc = xs[c & 1];
        float* sc = sout + (size_t)c * CHUNK * HID;

        for (int tl = 0; tl < CHUNK; tl += 2) {
            step(hbuf[0], hbuf[1], xc[tl],     sc + (size_t)tl * HID);
            step(hbuf[1], hbuf[0], xc[tl + 1], sc + (size_t)(tl + 1) * HID);
        }
    }
}

// no-op launch to align ncu's "-s 5 -c 1" onto the GRU kernel (5 mod 4 == 1)
__global__ void nop_kernel() {}

// out[n] = dot(states[n,:], w_lin) + b_lin + x[n]
#define HROWS 128
#define HPAD  65
__global__ void __launch_bounds__(128, 4)
head_kernel(const float* __restrict__ st, const float* __restrict__ x,
            const float* __restrict__ wl, const float* __restrict__ bl,
            float* __restrict__ out, int BT)
{
    __shared__ float tile[HROWS * HPAD];
    __shared__ float wsh[HID];

    const int tid = threadIdx.x;
    const size_t row0 = (size_t)blockIdx.x * HROWS;

    if (tid < HID) wsh[tid] = wl[tid];

    const float4* src = (const float4*)(st + row0 * HID);
    #pragma unroll
    for (int q = 0; q < (HROWS * HID / 4) / 128; q++) {
        int f4 = tid + q * 128;
        float4 v = src[f4];
        int flat = f4 * 4;
        int r = flat >> 6;
        int c = flat & 63;
        float* drow = &tile[r * HPAD + c];
        drow[0] = v.x; drow[1] = v.y; drow[2] = v.z; drow[3] = v.w;
    }
    __syncthreads();

    const float* trow = &tile[tid * HPAD];
    float acc = 0.0f;
    #pragma unroll
    for (int k = 0; k < HID; k++) acc = fmaf(trow[k], wsh[k], acc);

    size_t n = row0 + tid;
    out[n] = acc + bl[0] + x[n];
}

extern "C" void kernel_launch(void* const* d_in, const int* in_sizes, int n_in,
                              void* d_out, int out_size)
{
    const float* x     = (const float*)d_in[0];
    const float* w_ih  = (const float*)d_in[1];
    const float* w_hh  = (const float*)d_in[2];
    const float* b_ih  = (const float*)d_in[3];
    const float* b_hh  = (const float*)d_in[4];
    const float* w_lin = (const float*)d_in[5];
    const float* b_lin = (const float*)d_in[6];

    float* out = (float*)d_out;
    const int BT = in_sizes[0];          // B * T
    const int T  = BT / BATCH;
    float* states = out + BT;            // d_out = [out | states]

    nop_kernel<<<1, 32>>>();
    gru_kernel<<<BATCH, 128>>>(x, w_ih, w_hh, b_ih, b_hh, states, T);
    head_kernel<<<BT / HROWS, 128>>>(states, x, w_lin, b_lin, out, BT);
    nop_kernel<<<1, 32>>>();
}

// round 7
// speedup vs baseline: 1.0320x; 1.0320x over previous
#include <cuda_runtime.h>
#include <cstdint>

typedef unsigned long long u64;

#define BATCH 32
#define HID   64
#define CHUNK 2048
#define LOGC  11

__device__ __forceinline__ u64 fma2(u64 a, u64 b, u64 c){
    u64 d; asm("fma.rn.f32x2 %0, %1, %2, %3;" : "=l"(d) : "l"(a), "l"(b), "l"(c)); return d;
}
__device__ __forceinline__ u64 add2(u64 a, u64 b){
    u64 d; asm("add.rn.f32x2 %0, %1, %2;" : "=l"(d) : "l"(a), "l"(b)); return d;
}
__device__ __forceinline__ float hsum2(u64 a){
    float lo, hi; asm("mov.b64 {%0,%1}, %2;" : "=f"(lo), "=f"(hi) : "l"(a)); return lo + hi;
}
__device__ __forceinline__ float ex2f(float a){
    float d; asm("ex2.approx.f32 %0, %1;" : "=f"(d) : "f"(a)); return d;
}
__device__ __forceinline__ float rcpf(float a){
    float d; asm("rcp.approx.f32 %0, %1;" : "=f"(d) : "f"(a)); return d;
}

#define NEG_L2E (-1.4426950408889634f)
#define TWO_L2E  2.8853900817779268f

// One CTA per batch row (32 CTAs, each alone on an SM). 128 threads; pair
// (2i,2i+1) owns hidden unit i. Lane p=0: full 64-dot for r; p=1: full 64-dot
// for z; BOTH lanes: full 64-dot for n (duplicated -> no cross-lane shfl on
// the n path; tanh inputs are thread-local). Only z crosses lanes, consumed
// at the last FMA where it has ~80 cyc slack. Only p=0 stores h/states.
// h loaded once into registers, reused by both dots. ex2 args fused.
__global__ void __launch_bounds__(128, 1)
gru_kernel(const float* __restrict__ x, const float* __restrict__ w_ih,
           const float* __restrict__ w_hh, const float* __restrict__ b_ih,
           const float* __restrict__ b_hh, float* __restrict__ states, int T)
{
    __shared__ __align__(16) float hbuf[2][HID];
    __shared__ __align__(16) float xs[2][CHUNK];

    const int tid = threadIdx.x;
    const int b   = blockIdx.x;
    const int i   = tid >> 1;
    const int p   = tid & 1;
    const int ia  = i + 64 * p;        // r-row (p=0) or z-row (p=1)
    const int in_ = 128 + i;           // n-row

    // weights into registers (packed f32x2)
    u64 wa[32];
    {
        const u64* was = (const u64*)(w_hh + ia * 64);
        #pragma unroll
        for (int q = 0; q < 32; q++) wa[q] = was[q];
    }
    u64 wn[32];                         // FULL n-row on both lanes
    {
        const u64* wns = (const u64*)(w_hh + in_ * 64);
        #pragma unroll
        for (int q = 0; q < 32; q++) wn[q] = wns[q];
    }

    // fused activation constants
    const float ca    = b_hh[ia] + b_ih[ia];
    const float wihaL = w_ih[ia] * NEG_L2E;
    const float caL   = ca * NEG_L2E;
    const float wihn2 = w_ih[in_] * TWO_L2E;
    const float bihn2 = b_ih[in_] * TWO_L2E;
    const float bhhn2 = b_hh[in_] * TWO_L2E;

    const float* xrow = x + (size_t)b * T;

    if (tid < HID) hbuf[0][tid] = 0.0f;
    {
        const float4* src = (const float4*)xrow;
        float4* dst = (float4*)xs[0];
        #pragma unroll
        for (int q = 0; q < CHUNK / 4 / 128; q++) dst[tid + q * 128] = src[tid + q * 128];
    }
    __syncthreads();

    float* sout = states + ((size_t)b * T) * HID + i;
    float hprev = 0.0f;
    const int nch = T >> LOGC;

    auto step = [&](const float* hc, float* hd, float xt, float* sp) {
        const float xac = fmaf(xt, wihaL, caL);
        const float xn2 = fmaf(xt, wihn2, bihn2);

        // load h once (16 x LDS.128), reuse for both dots
        ulonglong2 hv[16];
        const ulonglong2* hs = (const ulonglong2*)hc;
        #pragma unroll
        for (int q = 0; q < 16; q++) hv[q] = hs[q];

        // full 64-dot for gate a (r or z)
        u64 a0=0,a1=0,a2=0,a3=0,a4=0,a5=0,a6=0,a7=0;
        #pragma unroll
        for (int q = 0; q < 4; q++) {
            a0 = fma2(hv[4*q].x,   wa[8*q],   a0);
            a1 = fma2(hv[4*q].y,   wa[8*q+1], a1);
            a2 = fma2(hv[4*q+1].x, wa[8*q+2], a2);
            a3 = fma2(hv[4*q+1].y, wa[8*q+3], a3);
            a4 = fma2(hv[4*q+2].x, wa[8*q+4], a4);
            a5 = fma2(hv[4*q+2].y, wa[8*q+5], a5);
            a6 = fma2(hv[4*q+3].x, wa[8*q+6], a6);
            a7 = fma2(hv[4*q+3].y, wa[8*q+7], a7);
        }
        float sa = hsum2(add2(add2(add2(a0,a1),add2(a2,a3)),
                              add2(add2(a4,a5),add2(a6,a7))));
        float ga = rcpf(1.0f + ex2f(fmaf(sa, NEG_L2E, xac)));   // sigma(own gate)
        float gz = __shfl_xor_sync(0xffffffffu, ga, 1);         // z for lane0 (slack-hidden)

        // full 64-dot for n-gate (duplicated on both lanes; overlaps sigma chain)
        u64 n0=0,n1=0,n2=0,n3=0,n4=0,n5=0,n6=0,n7=0;
        #pragma unroll
        for (int q = 0; q < 4; q++) {
            n0 = fma2(hv[4*q].x,   wn[8*q],   n0);
            n1 = fma2(hv[4*q].y,   wn[8*q+1], n1);
            n2 = fma2(hv[4*q+1].x, wn[8*q+2], n2);
            n3 = fma2(hv[4*q+1].y, wn[8*q+3], n3);
            n4 = fma2(hv[4*q+2].x, wn[8*q+4], n4);
            n5 = fma2(hv[4*q+2].y, wn[8*q+5], n5);
            n6 = fma2(hv[4*q+3].x, wn[8*q+6], n6);
            n7 = fma2(hv[4*q+3].y, wn[8*q+7], n7);
        }
        float sn = hsum2(add2(add2(add2(n0,n1),add2(n2,n3)),
                              add2(add2(n4,n5),add2(n6,n7))));

        // thread-local tanh tail with r := own sigma (real on lane0 only)
        float hn2 = fmaf(sn, TWO_L2E, bhhn2);
        float e2  = ex2f(fmaf(ga, hn2, xn2));
        float nv  = fmaf(-2.0f, rcpf(e2 + 1.0f), 1.0f);
        float hnew = fmaf(gz, hprev - nv, nv);      // (1-z)*n + z*h
        hprev = hnew;

        if (!p) {
            hd[i] = hnew;
            __stcs(sp, hnew);
        }
        __syncthreads();
    };

    for (int c = 0; c < nch; c++) {
        if (c + 1 < nch) {  // prefetch next x chunk: one branch per 2048 steps
            const float4* src = (const float4*)(xrow + (size_t)(c + 1) * CHUNK);
            float4* dst = (float4*)xs[(c + 1) & 1];
            #pragma unroll
            for (int q = 0; q < CHUNK / 4 / 128; q++) dst[tid + q * 128] = src[tid + q * 128];
        }
        const float* xc = xs[c & 1];
        float* sc = sout + (size_t)c * CHUNK * HID;

        for (int tl = 0; tl < CHUNK; tl += 2) {
            step(hbuf[0], hbuf[1], xc[tl],     sc + (size_t)tl * HID);
            step(hbuf[1], hbuf[0], xc[tl + 1], sc + (size_t)(tl + 1) * HID);
        }
    }
}

// out[n] = dot(states[n,:], w_lin) + b_lin + x[n]
#define HROWS 128
#define HPAD  65
__global__ void __launch_bounds__(128, 4)
head_kernel(const float* __restrict__ st, const float* __restrict__ x,
            const float* __restrict__ wl, const float* __restrict__ bl,
            float* __restrict__ out, int BT)
{
    __shared__ float tile[HROWS * HPAD];
    __shared__ float wsh[HID];

    const int tid = threadIdx.x;
    const size_t row0 = (size_t)blockIdx.x * HROWS;

    if (tid < HID) wsh[tid] = wl[tid];

    const float4* src = (const float4*)(st + row0 * HID);
    #pragma unroll
    for (int q = 0; q < (HROWS * HID / 4) / 128; q++) {
        int f4 = tid + q * 128;
        float4 v = src[f4];
        int flat = f4 * 4;
        int r = flat >> 6;
        int c = flat & 63;
        float* drow = &tile[r * HPAD + c];
        drow[0] = v.x; drow[1] = v.y; drow[2] = v.z; drow[3] = v.w;
    }
    __syncthreads();

    const float* trow = &tile[tid * HPAD];
    float acc = 0.0f;
    #pragma unroll
    for (int k = 0; k < HID; k++) acc = fmaf(trow[k], wsh[k], acc);

    size_t n = row0 + tid;
    out[n] = acc + bl[0] + x[n];
}

extern "C" void kernel_launch(void* const* d_in, const int* in_sizes, int n_in,
                              void* d_out, int out_size)
{
    const float* x     = (const float*)d_in[0];
    const float* w_ih  = (const float*)d_in[1];
    const float* w_hh  = (const float*)d_in[2];
    const float* b_ih  = (const float*)d_in[3];
    const float* b_hh  = (const float*)d_in[4];
    const float* w_lin = (const float*)d_in[5];
    const float* b_lin = (const float*)d_in[6];

    float* out = (float*)d_out;
    const int BT = in_sizes[0];          // B * T
    const int T  = BT / BATCH;
    float* states = out + BT;            // d_out = [out | states]

    gru_kernel<<<BATCH, 128>>>(x, w_ih, w_hh, b_ih, b_hh, states, T);
    head_kernel<<<BT / HROWS, 128>>>(states, x, w_lin, b_lin, out, BT);
}